// round 1
// baseline (speedup 1.0000x reference)
#include <cuda_runtime.h>
#include <cstdint>

#define FULL_MASK 0xffffffffu

// Problem geometry: (16, 1, 1024, 1024) fp32 pred/target, scalar fp32 out.
constexpr int W = 1024;
constexpr int H = 1024;
constexpr int PLANES = 16;

constexpr int OUT_COLS = 30;                       // valid outputs per 32-lane warp strip
constexpr int STRIPS   = (W + OUT_COLS - 1) / OUT_COLS;  // 35
constexpr int RY       = 64;                       // rows per warp band
constexpr int BANDS    = H / RY;                   // 16
constexpr int TOTAL_WARPS = STRIPS * BANDS * PLANES;     // 8960
constexpr int WPB      = 8;                        // warps per block (256 threads)
constexpr int NBLOCKS  = TOTAL_WARPS / WPB;        // 1120

// 81-scaled SSIM constants (mu = S/9; all /9 and /81 factors cancel in ratio)
constexpr float C1S = 81.0f * 0.0001f;   // 81 * 0.01^2
constexpr float C2S = 81.0f * 0.0009f;   // 81 * 0.03^2

__device__ float2 g_partials[TOTAL_WARPS];

__global__ void __launch_bounds__(WPB * 32)
loss_main(const float* __restrict__ pred, const float* __restrict__ targ)
{
    const int warp  = blockIdx.x * WPB + (threadIdx.x >> 5);
    const int lane  = threadIdx.x & 31;
    const int strip = warp % STRIPS;
    const int band  = (warp / STRIPS) % BANDS;
    const int plane = warp / (STRIPS * BANDS);

    // lane 0 and lane 31 are halo lanes; outputs come from lanes 1..30
    const int x = strip * OUT_COLS + lane - 1;
    const bool xin = ((unsigned)x < (unsigned)W);

    const float* __restrict__ pb = pred + (size_t)plane * (size_t)(W * H);
    const float* __restrict__ tb = targ + (size_t)plane * (size_t)(W * H);

    const int y0 = band * RY;

    // rotating 3-row window of horizontal 3-sums
    float hp0, ht0, hpp0, htt0, hpt0;
    float hp1, ht1, hpp1, htt1, hpt1;
    float pc, tc;   // center values of the "middle" row (for L1)

    // process one input row: load own column, shuffle x+-1, build horizontal sums
    auto row = [&](int y, float& hp, float& ht, float& hpp, float& htt, float& hpt,
                   float& pcen, float& tcen) {
        float p = 0.0f, t = 0.0f;
        if (xin && (unsigned)y < (unsigned)H) {
            p = __ldg(pb + y * W + x);
            t = __ldg(tb + y * W + x);
        }
        float pm = __shfl_up_sync(FULL_MASK, p, 1);
        float pp = __shfl_down_sync(FULL_MASK, p, 1);
        float tm = __shfl_up_sync(FULL_MASK, t, 1);
        float tp = __shfl_down_sync(FULL_MASK, t, 1);
        hp  = pm + p + pp;
        ht  = tm + t + tp;
        hpp = fmaf(pm, pm, fmaf(p, p, pp * pp));
        htt = fmaf(tm, tm, fmaf(t, t, tp * tp));
        hpt = fmaf(pm, tm, fmaf(p, t, pp * tp));
        pcen = p; tcen = t;
    };

    float dp, dt;
    row(y0 - 1, hp0, ht0, hpp0, htt0, hpt0, dp, dt);
    row(y0,     hp1, ht1, hpp1, htt1, hpt1, pc, tc);

    float ssim_acc = 0.0f;
    float l1_acc   = 0.0f;
    const bool valid = (lane >= 1) && (lane <= OUT_COLS) && (x < W);

    #pragma unroll 4
    for (int r = 0; r < RY; ++r) {
        const int y = y0 + r;
        float hp2, ht2, hpp2, htt2, hpt2, pc2, tc2;
        row(y + 1, hp2, ht2, hpp2, htt2, hpt2, pc2, tc2);

        // 3x3 window sums (x9 scale vs the means)
        const float SP  = hp0  + hp1  + hp2;
        const float ST  = ht0  + ht1  + ht2;
        const float SPP = hpp0 + hpp1 + hpp2;
        const float STT = htt0 + htt1 + htt2;
        const float SPT = hpt0 + hpt1 + hpt2;

        // SSIM on 81-scaled terms; scale factors cancel in the ratio
        const float A   = SP * ST;
        const float B   = SP * SP;
        const float Cq  = ST * ST;
        const float n1  = fmaf(2.0f, A, C1S);
        const float n2  = fmaf(18.0f, SPT, fmaf(-2.0f, A, C2S));
        const float BC  = B + Cq;
        const float d1  = BC + C1S;
        const float ts  = SPP + STT;
        const float d2  = fmaf(9.0f, ts, C2S) - BC;
        const float num = n1 * n2;
        const float den = d1 * d2;   // >= C1S*C2S > 0 always (Cauchy-Schwarz)
        const float ratio = __fdividef(num, den);
        float val = fmaf(ratio, -0.5f, 0.5f);
        val = fminf(fmaxf(val, 0.0f), 1.0f);
        const float l1v = fabsf(pc - tc);

        if (valid) {
            ssim_acc += val;
            l1_acc   += l1v;
        }

        // rotate window
        hp0 = hp1; ht0 = ht1; hpp0 = hpp1; htt0 = htt1; hpt0 = hpt1;
        hp1 = hp2; ht1 = ht2; hpp1 = hpp2; htt1 = htt2; hpt1 = hpt2;
        pc = pc2; tc = tc2;
    }

    // warp reduction of the two accumulators
    #pragma unroll
    for (int off = 16; off > 0; off >>= 1) {
        ssim_acc += __shfl_down_sync(FULL_MASK, ssim_acc, off);
        l1_acc   += __shfl_down_sync(FULL_MASK, l1_acc, off);
    }
    if (lane == 0) {
        g_partials[warp] = make_float2(ssim_acc, l1_acc);
    }
}

__global__ void __launch_bounds__(1024)
loss_reduce(float* __restrict__ out)
{
    __shared__ double s_ss[32];
    __shared__ double s_ll[32];
    const int tid  = threadIdx.x;
    const int lane = tid & 31;
    const int wid  = tid >> 5;

    double ss = 0.0, ll = 0.0;
    for (int i = tid; i < TOTAL_WARPS; i += 1024) {
        float2 v = g_partials[i];
        ss += (double)v.x;
        ll += (double)v.y;
    }
    #pragma unroll
    for (int off = 16; off > 0; off >>= 1) {
        ss += __shfl_down_sync(FULL_MASK, ss, off);
        ll += __shfl_down_sync(FULL_MASK, ll, off);
    }
    if (lane == 0) { s_ss[wid] = ss; s_ll[wid] = ll; }
    __syncthreads();
    if (wid == 0) {
        ss = (lane < 32) ? s_ss[lane] : 0.0;
        ll = (lane < 32) ? s_ll[lane] : 0.0;
        #pragma unroll
        for (int off = 16; off > 0; off >>= 1) {
            ss += __shfl_down_sync(FULL_MASK, ss, off);
            ll += __shfl_down_sync(FULL_MASK, ll, off);
        }
        if (lane == 0) {
            const double N = (double)PLANES * (double)W * (double)H;
            out[0] = (float)(0.85 * (ss / N) + 0.15 * (ll / N));
        }
    }
}

extern "C" void kernel_launch(void* const* d_in, const int* in_sizes, int n_in,
                              void* d_out, int out_size)
{
    const float* pred = (const float*)d_in[0];
    const float* targ = (const float*)d_in[1];
    float* out = (float*)d_out;

    loss_main<<<NBLOCKS, WPB * 32>>>(pred, targ);
    loss_reduce<<<1, 1024>>>(out);
}

// round 2
// speedup vs baseline: 1.5065x; 1.5065x over previous
#include <cuda_runtime.h>
#include <cstdint>

#define FULL_MASK 0xffffffffu

// Problem geometry: (16, 1, 1024, 1024) fp32 pred/target, scalar fp32 out.
constexpr int W = 1024;
constexpr int H = 1024;
constexpr int PLANES = 16;

// Each warp owns a 64-column aligned strip (2 cols per lane, float2 loads).
// Valid outputs: local cols 1..62 (62 per strip); strip 0 additionally emits
// local col 0 (image-left zero-pad), and the image-right pad comes from the
// clamped (zero) loads past col 1023.
constexpr int OUTC   = 62;
constexpr int STRIPS = 17;                 // 62*17 = 1054 >= 1024
constexpr int RY     = 64;                 // rows per warp band
constexpr int BANDS  = H / RY;             // 16
constexpr int TOTAL_WARPS = STRIPS * BANDS * PLANES;  // 4352
constexpr int WPB    = 8;                  // 256 threads per block
constexpr int NBLOCKS = TOTAL_WARPS / WPB; // 544

// 81-scaled SSIM constants (window SUMS instead of means; 81^2 cancels in ratio)
constexpr float C1S = 81.0f * 0.0001f;   // 81 * 0.01^2
constexpr float C2S = 81.0f * 0.0009f;   // 81 * 0.03^2

__device__ float2   g_partials[NBLOCKS];
__device__ unsigned g_count = 0;

__device__ __forceinline__ float ssim_val(float SP, float ST, float SPP,
                                          float STT, float SPT)
{
    const float A  = SP * ST;
    const float B  = SP * SP;
    const float Cq = ST * ST;
    const float n1 = fmaf(2.0f, A, C1S);
    const float n2 = fmaf(18.0f, SPT, fmaf(-2.0f, A, C2S));
    const float BC = B + Cq;
    const float d1 = BC + C1S;
    const float d2 = fmaf(9.0f, SPP + STT, C2S) - BC;
    const float r  = __fdividef(n1 * n2, d1 * d2);   // den >= C1S*C2S > 0
    float v = fmaf(r, -0.5f, 0.5f);
    return fminf(fmaxf(v, 0.0f), 1.0f);
}

__global__ void __launch_bounds__(WPB * 32)
loss_main(const float* __restrict__ pred, const float* __restrict__ targ,
          float* __restrict__ out)
{
    const int warp  = blockIdx.x * WPB + (threadIdx.x >> 5);
    const int lane  = threadIdx.x & 31;
    const int strip = warp % STRIPS;
    const int band  = (warp / STRIPS) % BANDS;
    const int plane = warp / (STRIPS * BANDS);

    const int x0  = strip * OUTC + 2 * lane;      // even -> float2 aligned
    const bool xin = (x0 < W);

    const float* __restrict__ pb = pred + (size_t)plane * (size_t)(W * H);
    const float* __restrict__ tb = targ + (size_t)plane * (size_t)(W * H);

    const int y0 = band * RY;

    // one input row -> horizontal 3-sums for the lane's 2 columns
    auto row = [&](int y, float2& hp, float2& ht, float2& hpp, float2& htt,
                   float2& hpt, float2& pcen, float2& tcen) {
        float2 p = make_float2(0.0f, 0.0f);
        float2 t = make_float2(0.0f, 0.0f);
        if (xin && (unsigned)y < (unsigned)H) {
            p = *(const float2*)(pb + y * W + x0);
            t = *(const float2*)(tb + y * W + x0);
        }
        float pL = __shfl_up_sync(FULL_MASK, p.y, 1);
        float tL = __shfl_up_sync(FULL_MASK, t.y, 1);
        float pR = __shfl_down_sync(FULL_MASK, p.x, 1);
        float tR = __shfl_down_sync(FULL_MASK, t.x, 1);
        if (lane == 0) { pL = 0.0f; tL = 0.0f; }   // image-left zero pad (strip 0)

        const float cp  = p.x + p.y;
        const float ct  = t.x + t.y;
        const float cpp = fmaf(p.x, p.x, p.y * p.y);
        const float ctt = fmaf(t.x, t.x, t.y * t.y);
        const float cpt = fmaf(p.x, t.x, p.y * t.y);

        hp  = make_float2(pL + cp,            cp + pR);
        ht  = make_float2(tL + ct,            ct + tR);
        hpp = make_float2(fmaf(pL, pL, cpp),  fmaf(pR, pR, cpp));
        htt = make_float2(fmaf(tL, tL, ctt),  fmaf(tR, tR, ctt));
        hpt = make_float2(fmaf(pL, tL, cpt),  fmaf(pR, tR, cpt));
        pcen = p; tcen = t;
    };

    float2 hp0, ht0, hpp0, htt0, hpt0;
    float2 hp1, ht1, hpp1, htt1, hpt1;
    float2 pc, tc, dp, dt;

    row(y0 - 1, hp0, ht0, hpp0, htt0, hpt0, dp, dt);
    row(y0,     hp1, ht1, hpp1, htt1, hpt1, pc, tc);

    const bool valid0 = ((lane > 0) || (strip == 0)) && (x0 < W);
    const bool valid1 = (lane < 31) && (x0 + 1 < W);

    float ssim_acc = 0.0f;
    float l1_acc   = 0.0f;

    #pragma unroll 2
    for (int r = 0; r < RY; ++r) {
        const int y = y0 + r;
        float2 hp2, ht2, hpp2, htt2, hpt2, pc2, tc2;
        row(y + 1, hp2, ht2, hpp2, htt2, hpt2, pc2, tc2);

        const float2 SP  = make_float2(hp0.x + hp1.x + hp2.x,   hp0.y + hp1.y + hp2.y);
        const float2 ST  = make_float2(ht0.x + ht1.x + ht2.x,   ht0.y + ht1.y + ht2.y);
        const float2 SPP = make_float2(hpp0.x + hpp1.x + hpp2.x, hpp0.y + hpp1.y + hpp2.y);
        const float2 STT = make_float2(htt0.x + htt1.x + htt2.x, htt0.y + htt1.y + htt2.y);
        const float2 SPT = make_float2(hpt0.x + hpt1.x + hpt2.x, hpt0.y + hpt1.y + hpt2.y);

        const float v0 = ssim_val(SP.x, ST.x, SPP.x, STT.x, SPT.x);
        const float v1 = ssim_val(SP.y, ST.y, SPP.y, STT.y, SPT.y);
        const float l0 = fabsf(pc.x - tc.x);
        const float l1 = fabsf(pc.y - tc.y);

        if (valid0) { ssim_acc += v0; l1_acc += l0; }
        if (valid1) { ssim_acc += v1; l1_acc += l1; }

        hp0 = hp1; ht0 = ht1; hpp0 = hpp1; htt0 = htt1; hpt0 = hpt1;
        hp1 = hp2; ht1 = ht2; hpp1 = hpp2; htt1 = htt2; hpt1 = hpt2;
        pc = pc2; tc = tc2;
    }

    // ---- warp reduce ----
    #pragma unroll
    for (int off = 16; off > 0; off >>= 1) {
        ssim_acc += __shfl_down_sync(FULL_MASK, ssim_acc, off);
        l1_acc   += __shfl_down_sync(FULL_MASK, l1_acc, off);
    }

    // ---- block reduce ----
    __shared__ float2 s_part[WPB];
    __shared__ bool   s_last;
    const int wid = threadIdx.x >> 5;
    if (lane == 0) s_part[wid] = make_float2(ssim_acc, l1_acc);
    __syncthreads();

    if (threadIdx.x == 0) {
        float ss = 0.0f, ll = 0.0f;
        #pragma unroll
        for (int i = 0; i < WPB; ++i) { ss += s_part[i].x; ll += s_part[i].y; }
        g_partials[blockIdx.x] = make_float2(ss, ll);
        __threadfence();
        const unsigned old = atomicAdd(&g_count, 1u);
        s_last = (old == (unsigned)(gridDim.x - 1));
    }
    __syncthreads();

    // ---- last block finishes the reduction (deterministic fixed-order sum) ----
    if (s_last) {
        double ss = 0.0, ll = 0.0;
        for (int i = threadIdx.x; i < NBLOCKS; i += WPB * 32) {
            const float2 v = g_partials[i];
            ss += (double)v.x;
            ll += (double)v.y;
        }
        #pragma unroll
        for (int off = 16; off > 0; off >>= 1) {
            ss += __shfl_down_sync(FULL_MASK, ss, off);
            ll += __shfl_down_sync(FULL_MASK, ll, off);
        }
        __shared__ double s_ss[WPB];
        __shared__ double s_ll[WPB];
        if (lane == 0) { s_ss[wid] = ss; s_ll[wid] = ll; }
        __syncthreads();
        if (threadIdx.x == 0) {
            double tss = 0.0, tll = 0.0;
            #pragma unroll
            for (int i = 0; i < WPB; ++i) { tss += s_ss[i]; tll += s_ll[i]; }
            const double N = (double)PLANES * (double)W * (double)H;
            out[0] = (float)(0.85 * (tss / N) + 0.15 * (tll / N));
            g_count = 0;   // reset for next graph replay
        }
    }
}

extern "C" void kernel_launch(void* const* d_in, const int* in_sizes, int n_in,
                              void* d_out, int out_size)
{
    const float* pred = (const float*)d_in[0];
    const float* targ = (const float*)d_in[1];
    float* out = (float*)d_out;

    loss_main<<<NBLOCKS, WPB * 32>>>(pred, targ, out);
}

// round 4
// speedup vs baseline: 1.5687x; 1.0413x over previous
#include <cuda_runtime.h>
#include <cstdint>

#define FULL_MASK 0xffffffffu
typedef unsigned long long u64;

// ---------- packed f32x2 helpers (sm_100+ SIMD fp32, PTX-only) ----------
__device__ __forceinline__ u64 pk(float lo, float hi) {
    u64 r; asm("mov.b64 %0,{%1,%2};" : "=l"(r) : "f"(lo), "f"(hi)); return r;
}
__device__ __forceinline__ void unpk(u64 v, float& lo, float& hi) {
    asm("mov.b64 {%0,%1},%2;" : "=f"(lo), "=f"(hi) : "l"(v));
}
__device__ __forceinline__ u64 add2(u64 a, u64 b) {
    u64 d; asm("add.rn.f32x2 %0,%1,%2;" : "=l"(d) : "l"(a), "l"(b)); return d;
}
__device__ __forceinline__ u64 mul2(u64 a, u64 b) {
    u64 d; asm("mul.rn.f32x2 %0,%1,%2;" : "=l"(d) : "l"(a), "l"(b)); return d;
}
__device__ __forceinline__ u64 fma2(u64 a, u64 b, u64 c) {
    u64 d; asm("fma.rn.f32x2 %0,%1,%2,%3;" : "=l"(d) : "l"(a), "l"(b), "l"(c)); return d;
}
__device__ __forceinline__ u64 abs2(u64 a) {   // clear both sign bits
    u64 d; asm("and.b64 %0,%1,0x7FFFFFFF7FFFFFFF;" : "=l"(d) : "l"(a)); return d;
}

// Problem geometry: (16, 1, 1024, 1024) fp32 pred/target, scalar fp32 out.
constexpr int W = 1024;
constexpr int H = 1024;
constexpr int PLANES = 16;

constexpr int OUTC   = 62;                 // valid outputs per 64-col warp strip
constexpr int STRIPS = 17;                 // 62*17 = 1054 >= 1024
constexpr int RY     = 64;                 // rows per warp band
constexpr int BANDS  = H / RY;             // 16
constexpr int TOTAL_WARPS = STRIPS * BANDS * PLANES;  // 4352
constexpr int WPB    = 8;                  // 256 threads per block
constexpr int NBLOCKS = TOTAL_WARPS / WPB; // 544

// 81-scaled SSIM constants (window SUMS instead of means; 81^2 cancels)
constexpr float C1S = 81.0f * 0.0001f;
constexpr float C2S = 81.0f * 0.0009f;

__device__ float2   g_partials[NBLOCKS];
__device__ unsigned g_count = 0;

__global__ void __launch_bounds__(WPB * 32)
loss_main(const float* __restrict__ pred, const float* __restrict__ targ,
          float* __restrict__ out)
{
    const int warp  = blockIdx.x * WPB + (threadIdx.x >> 5);
    const int lane  = threadIdx.x & 31;
    const int strip = warp % STRIPS;
    const int band  = (warp / STRIPS) % BANDS;
    const int plane = warp / (STRIPS * BANDS);

    const int x0  = strip * OUTC + 2 * lane;       // even -> 8B aligned
    const bool xin = (x0 < W);

    const float* __restrict__ pb = pred + (size_t)plane * (size_t)(W * H) + x0;
    const float* __restrict__ tb = targ + (size_t)plane * (size_t)(W * H) + x0;

    const int y0 = band * RY;

    // hoisted packed constants
    const u64 C1S2  = pk(C1S, C1S);
    const u64 C2S2  = pk(C2S, C2S);
    const u64 TWO2  = pk(2.0f, 2.0f);
    const u64 NEG22 = pk(-2.0f, -2.0f);
    const u64 E182  = pk(18.0f, 18.0f);
    const u64 NINE2 = pk(9.0f, 9.0f);
    const u64 NEG12 = pk(-1.0f, -1.0f);
    const u64 ZERO2 = pk(0.0f, 0.0f);

    const bool valid0 = ((lane > 0) || (strip == 0)) && (x0 < W);
    const bool valid1 = (lane < 31) && (x0 + 1 < W);
    const u64 MASK2 = pk(valid0 ? 1.0f : 0.0f, valid1 ? 1.0f : 0.0f);

    // one input row -> packed horizontal 3-sums for the lane's column pair
    auto row = [&](int y, u64& hp, u64& ht, u64& hpp, u64& htt, u64& hpt,
                   u64& p64o, u64& t64o) {
        u64 p64 = 0ull, t64 = 0ull;
        if (xin && (unsigned)y < (unsigned)H) {
            p64 = *(const u64*)(pb + (size_t)y * W);
            t64 = *(const u64*)(tb + (size_t)y * W);
        }
        float px, py, tx, ty;
        unpk(p64, px, py);
        unpk(t64, tx, ty);
        float pL = __shfl_up_sync(FULL_MASK, py, 1);
        float tL = __shfl_up_sync(FULL_MASK, ty, 1);
        float pR = __shfl_down_sync(FULL_MASK, px, 1);
        float tR = __shfl_down_sync(FULL_MASK, tx, 1);
        if (lane == 0) { pL = 0.0f; tL = 0.0f; }   // image-left zero pad

        const float cp  = px + py;
        const float ct  = tx + ty;
        const float cpp = fmaf(px, px, py * py);
        const float ctt = fmaf(tx, tx, ty * ty);
        const float cpt = fmaf(px, tx, py * ty);

        const u64 pLR = pk(pL, pR);
        const u64 tLR = pk(tL, tR);
        hp  = add2(pLR, pk(cp, cp));
        ht  = add2(tLR, pk(ct, ct));
        hpp = fma2(pLR, pLR, pk(cpp, cpp));
        htt = fma2(tLR, tLR, pk(ctt, ctt));
        hpt = fma2(pLR, tLR, pk(cpt, cpt));
        p64o = p64; t64o = t64;
    };

    u64 hp0, ht0, hpp0, htt0, hpt0;
    u64 hp1, ht1, hpp1, htt1, hpt1;
    u64 pc, tc, dp, dt;

    row(y0 - 1, hp0, ht0, hpp0, htt0, hpt0, dp, dt);
    row(y0,     hp1, ht1, hpp1, htt1, hpt1, pc, tc);

    u64 ssim_acc = ZERO2;
    u64 l1_acc   = ZERO2;

    #pragma unroll 4
    for (int r = 0; r < RY; ++r) {
        const int y = y0 + r;
        u64 hp2, ht2, hpp2, htt2, hpt2, pc2, tc2;
        row(y + 1, hp2, ht2, hpp2, htt2, hpt2, pc2, tc2);

        // packed 3x3 window sums
        const u64 SP  = add2(add2(hp0,  hp1),  hp2);
        const u64 ST  = add2(add2(ht0,  ht1),  ht2);
        const u64 SPP = add2(add2(hpp0, hpp1), hpp2);
        const u64 STT = add2(add2(htt0, htt1), htt2);
        const u64 SPT = add2(add2(hpt0, hpt1), hpt2);

        // packed SSIM polynomial (81-scaled)
        const u64 A   = mul2(SP, ST);
        const u64 B   = mul2(SP, SP);
        const u64 Cq  = mul2(ST, ST);
        const u64 n1  = fma2(TWO2, A, C1S2);
        const u64 n2  = fma2(E182, SPT, fma2(NEG22, A, C2S2));
        const u64 BC  = add2(B, Cq);
        const u64 d1  = add2(BC, C1S2);
        const u64 ts  = add2(SPP, STT);
        const u64 d2  = fma2(BC, NEG12, fma2(NINE2, ts, C2S2));
        const u64 num = mul2(n1, n2);
        const u64 den = mul2(d1, d2);    // >= C1S*C2S > 0

        float nx, ny, dx, dy;
        unpk(num, nx, ny);
        unpk(den, dx, dy);
        const float r0 = __fdividef(nx, dx);
        const float r1 = __fdividef(ny, dy);

        // val = clamp(0.5 - 0.5*r, 0, 1); scalar clamp (no f32x2 min/max in PTX)
        float v0 = fmaf(r0, -0.5f, 0.5f);
        float v1 = fmaf(r1, -0.5f, 0.5f);
        v0 = fminf(fmaxf(v0, 0.0f), 1.0f);
        v1 = fminf(fmaxf(v1, 0.0f), 1.0f);

        ssim_acc = fma2(pk(v0, v1), MASK2, ssim_acc);

        const u64 df = abs2(fma2(tc, NEG12, pc));
        l1_acc = fma2(df, MASK2, l1_acc);

        hp0 = hp1; ht0 = ht1; hpp0 = hpp1; htt0 = htt1; hpt0 = hpt1;
        hp1 = hp2; ht1 = ht2; hpp1 = hpp2; htt1 = htt2; hpt1 = hpt2;
        pc = pc2; tc = tc2;
    }

    // fold packed pair -> scalars
    float s_lo, s_hi, l_lo, l_hi;
    unpk(ssim_acc, s_lo, s_hi);
    unpk(l1_acc,   l_lo, l_hi);
    float ssim_s = s_lo + s_hi;
    float l1_s   = l_lo + l_hi;

    // ---- warp reduce ----
    #pragma unroll
    for (int off = 16; off > 0; off >>= 1) {
        ssim_s += __shfl_down_sync(FULL_MASK, ssim_s, off);
        l1_s   += __shfl_down_sync(FULL_MASK, l1_s, off);
    }

    // ---- block reduce ----
    __shared__ float2 s_part[WPB];
    __shared__ bool   s_last;
    const int wid = threadIdx.x >> 5;
    if (lane == 0) s_part[wid] = make_float2(ssim_s, l1_s);
    __syncthreads();

    if (threadIdx.x == 0) {
        float ss = 0.0f, ll = 0.0f;
        #pragma unroll
        for (int i = 0; i < WPB; ++i) { ss += s_part[i].x; ll += s_part[i].y; }
        g_partials[blockIdx.x] = make_float2(ss, ll);
        __threadfence();
        const unsigned old = atomicAdd(&g_count, 1u);
        s_last = (old == (unsigned)(gridDim.x - 1));
    }
    __syncthreads();

    // ---- last block: deterministic final reduction ----
    if (s_last) {
        double ss = 0.0, ll = 0.0;
        for (int i = threadIdx.x; i < NBLOCKS; i += WPB * 32) {
            const float2 v = g_partials[i];
            ss += (double)v.x;
            ll += (double)v.y;
        }
        #pragma unroll
        for (int off = 16; off > 0; off >>= 1) {
            ss += __shfl_down_sync(FULL_MASK, ss, off);
            ll += __shfl_down_sync(FULL_MASK, ll, off);
        }
        __shared__ double s_ss[WPB];
        __shared__ double s_ll[WPB];
        if (lane == 0) { s_ss[wid] = ss; s_ll[wid] = ll; }
        __syncthreads();
        if (threadIdx.x == 0) {
            double tss = 0.0, tll = 0.0;
            #pragma unroll
            for (int i = 0; i < WPB; ++i) { tss += s_ss[i]; tll += s_ll[i]; }
            const double N = (double)PLANES * (double)W * (double)H;
            out[0] = (float)(0.85 * (tss / N) + 0.15 * (tll / N));
            g_count = 0;   // reset for next graph replay
        }
    }
}

extern "C" void kernel_launch(void* const* d_in, const int* in_sizes, int n_in,
                              void* d_out, int out_size)
{
    const float* pred = (const float*)d_in[0];
    const float* targ = (const float*)d_in[1];
    float* out = (float*)d_out;

    loss_main<<<NBLOCKS, WPB * 32>>>(pred, targ, out);
}